// round 1
// baseline (speedup 1.0000x reference)
#include <cuda_runtime.h>
#include <cuda_bf16.h>

// Problem constants (fixed by the reference)
#define BATCH 524288
#define NFEAT 8

// Precomputed contraction tensor: out = sum_{a,b,c} T[a*9+b*3+c] * v0_a*v1_b*v2_c
// with v_i = (1, cos x_i, sin x_i)
__device__ float d_T[27];

// g(basis, jb, kb): coefficient mapping the per-qubit monomial t[jb]*t[kb]
// (t = (cos th/2, sin th/2)) onto basis (1, cos th, sin th):
//   c^2 = 0.5 + 0.5 cos ; s^2 = 0.5 - 0.5 cos ; c*s = 0.5 sin
__device__ __forceinline__ float gfun(int basis, int jb, int kb) {
    if (basis == 2) return (jb != kb) ? 0.5f : 0.0f;
    if (jb != kb) return 0.0f;
    if (basis == 0) return 0.5f;
    return jb ? -0.5f : 0.5f;
}

// One block, 64 threads: build V (variational unitary), M = Re(V^H Z0 V), then T.
__global__ void vqc_setup_kernel(const float* __restrict__ w) {
    __shared__ float Vr[8][8];  // Vr[row][col]
    __shared__ float Vi[8][8];
    __shared__ float Ms[8][8];

    const int t = threadIdx.x;

    if (t < 8) {
        // Simulate column t of V through the 3 variational layers.
        float re[8], im[8];
#pragma unroll
        for (int k = 0; k < 8; k++) { re[k] = 0.0f; im[k] = 0.0f; }
        re[t] = 1.0f;

#pragma unroll
        for (int l = 0; l < 3; l++) {
#pragma unroll
            for (int q = 0; q < 3; q++) {
                const float th = w[(l * 3 + q) * 2 + 0];
                const float ph = w[(l * 3 + q) * 2 + 1];
                float cy, sy, cz, sz;
                sincosf(0.5f * th, &sy, &cy);
                sincosf(0.5f * ph, &sz, &cz);
                const int bit = 4 >> q;  // qubit q occupies bit (2-q)
#pragma unroll
                for (int j = 0; j < 8; j++) {
                    if (j & bit) continue;
                    const int j1 = j | bit;
                    const float r0 = re[j],  i0 = im[j];
                    const float r1 = re[j1], i1 = im[j1];
                    // RY(th)
                    const float nr0 = cy * r0 - sy * r1;
                    const float ni0 = cy * i0 - sy * i1;
                    const float nr1 = sy * r0 + cy * r1;
                    const float ni1 = sy * i0 + cy * i1;
                    // RZ(ph): amp(bit=0) *= cz - i sz ; amp(bit=1) *= cz + i sz
                    re[j]  = cz * nr0 + sz * ni0;
                    im[j]  = cz * ni0 - sz * nr0;
                    re[j1] = cz * nr1 - sz * ni1;
                    im[j1] = cz * ni1 + sz * nr1;
                }
            }
            // CNOT(0,1): control bit4, target bit2
#pragma unroll
            for (int j = 0; j < 8; j++) {
                if ((j & 4) && !(j & 2)) {
                    const int j1 = j | 2;
                    float tmp;
                    tmp = re[j]; re[j] = re[j1]; re[j1] = tmp;
                    tmp = im[j]; im[j] = im[j1]; im[j1] = tmp;
                }
            }
            // CNOT(1,2): control bit2, target bit1
#pragma unroll
            for (int j = 0; j < 8; j++) {
                if ((j & 2) && !(j & 1)) {
                    const int j1 = j | 1;
                    float tmp;
                    tmp = re[j]; re[j] = re[j1]; re[j1] = tmp;
                    tmp = im[j]; im[j] = im[j1]; im[j1] = tmp;
                }
            }
        }
#pragma unroll
        for (int r = 0; r < 8; r++) { Vr[r][t] = re[r]; Vi[r][t] = im[r]; }
    }
    __syncthreads();

    if (t < 64) {
        // M[j][k] = sum_r z_r * Re(conj(V[r][j]) * V[r][k]),  z_r = +1 (r<4) else -1
        const int j = t >> 3, k = t & 7;
        float m = 0.0f;
#pragma unroll
        for (int r = 0; r < 8; r++) {
            const float zr = (r < 4) ? 1.0f : -1.0f;
            m += zr * (Vr[r][j] * Vr[r][k] + Vi[r][j] * Vi[r][k]);
        }
        Ms[j][k] = m;
    }
    __syncthreads();

    if (t < 27) {
        const int a = t / 9, b = (t / 3) % 3, c = t % 3;
        float acc = 0.0f;
#pragma unroll
        for (int j = 0; j < 8; j++) {
#pragma unroll
            for (int k = 0; k < 8; k++) {
                const float g = gfun(a, (j >> 2) & 1, (k >> 2) & 1) *
                                gfun(b, (j >> 1) & 1, (k >> 1) & 1) *
                                gfun(c, j & 1, k & 1);
                acc += g * Ms[j][k];
            }
        }
        d_T[t] = acc;
    }
}

#define TPB 128
#define EPT 4

__global__ void __launch_bounds__(TPB) vqc_main_kernel(
    const float4* __restrict__ x4, float4* __restrict__ out4) {

    // Load the 27-coefficient tensor once per thread (amortized over EPT elements).
    float T[27];
#pragma unroll
    for (int i = 0; i < 27; i++) T[i] = __ldg(&d_T[i]);

    const int gtid = blockIdx.x * TPB + threadIdx.x;
    const int base = gtid * EPT;

    float res[EPT];
#pragma unroll
    for (int e = 0; e < EPT; e++) {
        const int idx = base + e;
        // row idx of x: 8 floats = 2 float4; only the first 3 floats are used
        const float4 xv = x4[idx * 2];
        float c0, s0, c1, s1, c2, s2;
        __sincosf(xv.x, &s0, &c0);
        __sincosf(xv.y, &s1, &c1);
        __sincosf(xv.z, &s2, &c2);

        float u[3];
#pragma unroll
        for (int a = 0; a < 3; a++) {
            float wb[3];
#pragma unroll
            for (int b = 0; b < 3; b++) {
                const float* Tb = &T[a * 9 + b * 3];
                wb[b] = Tb[0] + Tb[1] * c2 + Tb[2] * s2;
            }
            u[a] = wb[0] + wb[1] * c1 + wb[2] * s1;
        }
        res[e] = u[0] + u[1] * c0 + u[2] * s0;
    }

    out4[gtid] = make_float4(res[0], res[1], res[2], res[3]);
}

extern "C" void kernel_launch(void* const* d_in, const int* in_sizes, int n_in,
                              void* d_out, int out_size) {
    const float* x = (const float*)d_in[0];        // [BATCH, 8]
    const float* w = (const float*)d_in[1];        // [3, 3, 2]
    float* out = (float*)d_out;                    // [BATCH, 1]

    vqc_setup_kernel<<<1, 64>>>(w);

    const int nblocks = BATCH / (TPB * EPT);       // 1024
    vqc_main_kernel<<<nblocks, TPB>>>((const float4*)x, (float4*)out);
}

// round 2
// speedup vs baseline: 1.1846x; 1.1846x over previous
#include <cuda_runtime.h>
#include <cuda_bf16.h>

// Problem constants (fixed by the reference)
#define BATCH 524288
#define NFEAT 8

// Precomputed contraction tensor: out = sum_{a,b,c} T[a*9+b*3+c] * v0_a*v1_b*v2_c
// with v_i = (1, cos x_i, sin x_i)
__device__ float d_T[27];

// g(basis, jb, kb): coefficient mapping the per-qubit monomial t[jb]*t[kb]
// (t = (cos th/2, sin th/2)) onto basis (1, cos th, sin th):
//   c^2 = 0.5 + 0.5 cos ; s^2 = 0.5 - 0.5 cos ; c*s = 0.5 sin
__device__ __forceinline__ float gfun(int basis, int jb, int kb) {
    if (basis == 2) return (jb != kb) ? 0.5f : 0.0f;
    if (jb != kb) return 0.0f;
    if (basis == 0) return 0.5f;
    return jb ? -0.5f : 0.5f;
}

// One block, 64 threads: build V (variational unitary), M = Re(V^H Z0 V), then T.
__global__ void vqc_setup_kernel(const float* __restrict__ w) {
    __shared__ float Vr[8][8];  // Vr[row][col]
    __shared__ float Vi[8][8];
    __shared__ float Ms[8][8];

    const int t = threadIdx.x;

    if (t < 8) {
        // Simulate column t of V through the 3 variational layers.
        float re[8], im[8];
#pragma unroll
        for (int k = 0; k < 8; k++) { re[k] = 0.0f; im[k] = 0.0f; }
        re[t] = 1.0f;

#pragma unroll
        for (int l = 0; l < 3; l++) {
#pragma unroll
            for (int q = 0; q < 3; q++) {
                const float th = w[(l * 3 + q) * 2 + 0];
                const float ph = w[(l * 3 + q) * 2 + 1];
                float cy, sy, cz, sz;
                sincosf(0.5f * th, &sy, &cy);
                sincosf(0.5f * ph, &sz, &cz);
                const int bit = 4 >> q;  // qubit q occupies bit (2-q)
#pragma unroll
                for (int j = 0; j < 8; j++) {
                    if (j & bit) continue;
                    const int j1 = j | bit;
                    const float r0 = re[j],  i0 = im[j];
                    const float r1 = re[j1], i1 = im[j1];
                    // RY(th)
                    const float nr0 = cy * r0 - sy * r1;
                    const float ni0 = cy * i0 - sy * i1;
                    const float nr1 = sy * r0 + cy * r1;
                    const float ni1 = sy * i0 + cy * i1;
                    // RZ(ph): amp(bit=0) *= cz - i sz ; amp(bit=1) *= cz + i sz
                    re[j]  = cz * nr0 + sz * ni0;
                    im[j]  = cz * ni0 - sz * nr0;
                    re[j1] = cz * nr1 - sz * ni1;
                    im[j1] = cz * ni1 + sz * nr1;
                }
            }
            // CNOT(0,1): control bit4, target bit2
#pragma unroll
            for (int j = 0; j < 8; j++) {
                if ((j & 4) && !(j & 2)) {
                    const int j1 = j | 2;
                    float tmp;
                    tmp = re[j]; re[j] = re[j1]; re[j1] = tmp;
                    tmp = im[j]; im[j] = im[j1]; im[j1] = tmp;
                }
            }
            // CNOT(1,2): control bit2, target bit1
#pragma unroll
            for (int j = 0; j < 8; j++) {
                if ((j & 2) && !(j & 1)) {
                    const int j1 = j | 1;
                    float tmp;
                    tmp = re[j]; re[j] = re[j1]; re[j1] = tmp;
                    tmp = im[j]; im[j] = im[j1]; im[j1] = tmp;
                }
            }
        }
#pragma unroll
        for (int r = 0; r < 8; r++) { Vr[r][t] = re[r]; Vi[r][t] = im[r]; }
    }
    __syncthreads();

    if (t < 64) {
        // M[j][k] = sum_r z_r * Re(conj(V[r][j]) * V[r][k]),  z_r = +1 (r<4) else -1
        const int j = t >> 3, k = t & 7;
        float m = 0.0f;
#pragma unroll
        for (int r = 0; r < 8; r++) {
            const float zr = (r < 4) ? 1.0f : -1.0f;
            m += zr * (Vr[r][j] * Vr[r][k] + Vi[r][j] * Vi[r][k]);
        }
        Ms[j][k] = m;
    }
    __syncthreads();

    if (t < 27) {
        const int a = t / 9, b = (t / 3) % 3, c = t % 3;
        float acc = 0.0f;
#pragma unroll
        for (int j = 0; j < 8; j++) {
#pragma unroll
            for (int k = 0; k < 8; k++) {
                const float g = gfun(a, (j >> 2) & 1, (k >> 2) & 1) *
                                gfun(b, (j >> 1) & 1, (k >> 1) & 1) *
                                gfun(c, j & 1, k & 1);
                acc += g * Ms[j][k];
            }
        }
        d_T[t] = acc;
    }
}

#define TPB 256
#define EPT 2

__global__ void __launch_bounds__(TPB) vqc_main_kernel(
    const float4* __restrict__ x4, float* __restrict__ out) {

    // Consecutive lanes handle consecutive rows -> warp-LDG spans 8 lines, not 32.
    const int base = blockIdx.x * (TPB * EPT) + threadIdx.x;

    // Issue both row loads up front (MLP=2, independent).
    float4 xv[EPT];
#pragma unroll
    for (int e = 0; e < EPT; e++) {
        xv[e] = x4[2 * (base + e * TPB)];  // first 16B of each 32B row
    }

    // Load the 27-coefficient tensor (uniform -> L1 broadcast).
    float T[27];
#pragma unroll
    for (int i = 0; i < 27; i++) T[i] = __ldg(&d_T[i]);

#pragma unroll
    for (int e = 0; e < EPT; e++) {
        float c0, s0, c1, s1, c2, s2;
        __sincosf(xv[e].x, &s0, &c0);
        __sincosf(xv[e].y, &s1, &c1);
        __sincosf(xv[e].z, &s2, &c2);

        float u[3];
#pragma unroll
        for (int a = 0; a < 3; a++) {
            float wb[3];
#pragma unroll
            for (int b = 0; b < 3; b++) {
                const float* Tb = &T[a * 9 + b * 3];
                wb[b] = Tb[0] + Tb[1] * c2 + Tb[2] * s2;
            }
            u[a] = wb[0] + wb[1] * c1 + wb[2] * s1;
        }
        out[base + e * TPB] = u[0] + u[1] * c0 + u[2] * s0;
    }
}

extern "C" void kernel_launch(void* const* d_in, const int* in_sizes, int n_in,
                              void* d_out, int out_size) {
    const float* x = (const float*)d_in[0];        // [BATCH, 8]
    const float* w = (const float*)d_in[1];        // [3, 3, 2]
    float* out = (float*)d_out;                    // [BATCH, 1]

    vqc_setup_kernel<<<1, 64>>>(w);

    const int nblocks = BATCH / (TPB * EPT);       // 1024
    vqc_main_kernel<<<nblocks, TPB>>>((const float4*)x, out);
}

// round 3
// speedup vs baseline: 1.3949x; 1.1775x over previous
#include <cuda_runtime.h>
#include <cuda_bf16.h>

// Problem constants (fixed by the reference)
#define BATCH 524288
#define NFEAT 8
#define TPB 128
#define EPT 4

// g(basis, jb, kb): coefficient mapping per-qubit monomial t[jb]*t[kb]
// (t = (cos th/2, sin th/2)) onto basis (1, cos th, sin th):
//   c^2 = 0.5 + 0.5 cos ; s^2 = 0.5 - 0.5 cos ; c*s = 0.5 sin
__device__ __forceinline__ float gfun(int basis, int jb, int kb) {
    if (basis == 2) return (jb != kb) ? 0.5f : 0.0f;
    if (jb != kb) return 0.0f;
    if (basis == 0) return 0.5f;
    return jb ? -0.5f : 0.5f;
}

// Fused kernel: each block (redundantly) computes the 27-coeff contraction
// tensor T from the weights while its batch loads are in flight, then applies
// out = sum_{a,b,c} T[a,b,c] * v0_a * v1_b * v2_c, v_i = (1, cos x_i, sin x_i).
__global__ void __launch_bounds__(TPB) vqc_fused_kernel(
    const float4* __restrict__ x4, float* __restrict__ out,
    const float* __restrict__ w) {

    __shared__ float Vr[8][8];
    __shared__ float Vi[8][8];
    __shared__ float Ms[8][8];
    __shared__ float sT[27];

    const int tid = threadIdx.x;
    const int base = blockIdx.x * (TPB * EPT) + tid;

    // ---- Issue all batch loads FIRST (4 independent LDG.128, fly during setup) ----
    float4 xv[EPT];
#pragma unroll
    for (int e = 0; e < EPT; e++) {
        xv[e] = x4[2 * (base + e * TPB)];  // first 16B of each 32B row
    }

    // ---- Per-block setup: build V, M = Re(V^H Z0 V), then T (overlaps load latency) ----
    if (tid < 8) {
        float re[8], im[8];
#pragma unroll
        for (int k = 0; k < 8; k++) { re[k] = 0.0f; im[k] = 0.0f; }
        re[tid] = 1.0f;

#pragma unroll
        for (int l = 0; l < 3; l++) {
#pragma unroll
            for (int q = 0; q < 3; q++) {
                const float th = w[(l * 3 + q) * 2 + 0];
                const float ph = w[(l * 3 + q) * 2 + 1];
                float cy, sy, cz, sz;
                __sincosf(0.5f * th, &sy, &cy);
                __sincosf(0.5f * ph, &sz, &cz);
                const int bit = 4 >> q;  // qubit q occupies bit (2-q)
#pragma unroll
                for (int j = 0; j < 8; j++) {
                    if (j & bit) continue;
                    const int j1 = j | bit;
                    const float r0 = re[j],  i0 = im[j];
                    const float r1 = re[j1], i1 = im[j1];
                    // RY(th)
                    const float nr0 = cy * r0 - sy * r1;
                    const float ni0 = cy * i0 - sy * i1;
                    const float nr1 = sy * r0 + cy * r1;
                    const float ni1 = sy * i0 + cy * i1;
                    // RZ(ph)
                    re[j]  = cz * nr0 + sz * ni0;
                    im[j]  = cz * ni0 - sz * nr0;
                    re[j1] = cz * nr1 - sz * ni1;
                    im[j1] = cz * ni1 + sz * nr1;
                }
            }
            // CNOT(0,1): control bit4, target bit2
#pragma unroll
            for (int j = 0; j < 8; j++) {
                if ((j & 4) && !(j & 2)) {
                    const int j1 = j | 2;
                    float tmp;
                    tmp = re[j]; re[j] = re[j1]; re[j1] = tmp;
                    tmp = im[j]; im[j] = im[j1]; im[j1] = tmp;
                }
            }
            // CNOT(1,2): control bit2, target bit1
#pragma unroll
            for (int j = 0; j < 8; j++) {
                if ((j & 2) && !(j & 1)) {
                    const int j1 = j | 1;
                    float tmp;
                    tmp = re[j]; re[j] = re[j1]; re[j1] = tmp;
                    tmp = im[j]; im[j] = im[j1]; im[j1] = tmp;
                }
            }
        }
#pragma unroll
        for (int r = 0; r < 8; r++) { Vr[r][tid] = re[r]; Vi[r][tid] = im[r]; }
    }
    __syncthreads();

    if (tid < 64) {
        const int j = tid >> 3, k = tid & 7;
        float m = 0.0f;
#pragma unroll
        for (int r = 0; r < 8; r++) {
            const float zr = (r < 4) ? 1.0f : -1.0f;
            m += zr * (Vr[r][j] * Vr[r][k] + Vi[r][j] * Vi[r][k]);
        }
        Ms[j][k] = m;
    }
    __syncthreads();

    if (tid < 27) {
        const int a = tid / 9, b = (tid / 3) % 3, c = tid % 3;
        float acc = 0.0f;
#pragma unroll
        for (int j = 0; j < 8; j++) {
#pragma unroll
            for (int k = 0; k < 8; k++) {
                const float g = gfun(a, (j >> 2) & 1, (k >> 2) & 1) *
                                gfun(b, (j >> 1) & 1, (k >> 1) & 1) *
                                gfun(c, j & 1, k & 1);
                acc += g * Ms[j][k];
            }
        }
        sT[tid] = acc;
    }
    __syncthreads();

    // ---- Main compute: T from smem (broadcast), 4 independent chains ----
    float T[27];
#pragma unroll
    for (int i = 0; i < 27; i++) T[i] = sT[i];

#pragma unroll
    for (int e = 0; e < EPT; e++) {
        float c0, s0, c1, s1, c2, s2;
        __sincosf(xv[e].x, &s0, &c0);
        __sincosf(xv[e].y, &s1, &c1);
        __sincosf(xv[e].z, &s2, &c2);

        float u[3];
#pragma unroll
        for (int a = 0; a < 3; a++) {
            float wb[3];
#pragma unroll
            for (int b = 0; b < 3; b++) {
                const float* Tb = &T[a * 9 + b * 3];
                wb[b] = Tb[0] + Tb[1] * c2 + Tb[2] * s2;
            }
            u[a] = wb[0] + wb[1] * c1 + wb[2] * s1;
        }
        out[base + e * TPB] = u[0] + u[1] * c0 + u[2] * s0;
    }
}

extern "C" void kernel_launch(void* const* d_in, const int* in_sizes, int n_in,
                              void* d_out, int out_size) {
    const float* x = (const float*)d_in[0];        // [BATCH, 8]
    const float* w = (const float*)d_in[1];        // [3, 3, 2]
    float* out = (float*)d_out;                    // [BATCH, 1]

    const int nblocks = BATCH / (TPB * EPT);       // 1024
    vqc_fused_kernel<<<nblocks, TPB>>>((const float4*)x, out, w);
}